// round 3
// baseline (speedup 1.0000x reference)
#include <cuda_runtime.h>
#include <cuda_bf16.h>
#include <cstdint>

// ============================================================================
// out[64,8] = exp(-1e-4 * ||x_b - c_j||^2) @ fc_w.T + fc_b
//   x: [64, 65536] f32, centers: [500, 65536] f32
// K1: split-K (128 chunks of 512). Per CTA: f32->bf16 convert into SW128 smem,
//     warp-level mma.sync bf16 (128 centers x 64 batch per block, 4 blocks),
//     fp32 partials to gmem. Exact fp32 sum-of-squares fused into conversion.
// K2/K3/K4: finalize norms, reduce partials -> rbf, fc head.
// Base sm_100 only: mma.sync + ldmatrix (harness compiles to compute_100,
// so no tcgen05 / 'a' features).
// ============================================================================

#define GAMMA_F 1e-4f

static constexpr int S_SPLIT = 128;   // K chunks
static constexpr int KC      = 512;   // K per chunk
static constexpr int NB      = 64;    // batch (N)
static constexpr int MC      = 128;   // centers per block (M)
static constexpr int NCBLK   = 4;
static constexpr int NCPAD   = 512;

// -------- scratch (device globals; allocation-free) --------
__device__ float g_part [(size_t)NCPAD * S_SPLIT * NB];   // 16 MB cross partials
__device__ float g_csq_p[(size_t)NCPAD * S_SPLIT];
__device__ float g_xsq_p[(size_t)NB    * S_SPLIT];
__device__ float g_csq  [NCPAD];
__device__ float g_xsq  [NB];
__device__ float g_rbf  [(size_t)NB * NCPAD];

// -------- helpers --------
__device__ __forceinline__ uint32_t smem_u32(const void* p) {
    uint32_t a;
    asm("{ .reg .u64 t; cvta.to.shared.u64 t, %1; cvt.u32.u64 %0, t; }" : "=r"(a) : "l"(p));
    return a;
}
__device__ __forceinline__ uint32_t sw128(uint32_t off) { return off ^ ((off >> 3) & 0x70); }

// blocked-atom byte offsets (atom = 8 rows x 64 bf16 = 1024B), then SW128 swizzle
// x tile: 64 rows (8 atom rows per k-column-block), c tile: 128 rows (16 atom rows)
__device__ __forceinline__ uint32_t x_off(int row, int k) {
    uint32_t b = (((uint32_t)(k >> 6) * 8u + (uint32_t)(row >> 3)) << 10)
               + (uint32_t)(row & 7) * 128u + (uint32_t)(k & 63) * 2u;
    return sw128(b);
}
__device__ __forceinline__ uint32_t c_off(int row, int k) {
    uint32_t b = (((uint32_t)(k >> 6) * 16u + (uint32_t)(row >> 3)) << 10)
               + (uint32_t)(row & 7) * 128u + (uint32_t)(k & 63) * 2u;
    return sw128(b);
}
__device__ __forceinline__ uint32_t pack_bf16x2(float a, float b) {
    __nv_bfloat162 t = __floats2bfloat162_rn(a, b);
    return *reinterpret_cast<uint32_t*>(&t);
}

__device__ __forceinline__ void ldsm_x4(uint32_t* r, uint32_t addr) {
    asm volatile("ldmatrix.sync.aligned.m8n8.x4.shared.b16 {%0,%1,%2,%3}, [%4];"
                 : "=r"(r[0]), "=r"(r[1]), "=r"(r[2]), "=r"(r[3]) : "r"(addr));
}
__device__ __forceinline__ void mma_bf16(float* d, const uint32_t* a, const uint32_t* b) {
    asm volatile("mma.sync.aligned.m16n8k16.row.col.f32.bf16.bf16.f32 "
                 "{%0,%1,%2,%3}, {%4,%5,%6,%7}, {%8,%9}, {%0,%1,%2,%3};"
                 : "+f"(d[0]), "+f"(d[1]), "+f"(d[2]), "+f"(d[3])
                 : "r"(a[0]), "r"(a[1]), "r"(a[2]), "r"(a[3]), "r"(b[0]), "r"(b[1]));
}

// -------- SMEM layout (dynamic) --------
static constexpr int SMEM_X     = 0;                       // 64 x 512 bf16 = 64 KB
static constexpr int SMEM_C     = 64 * KC * 2;             // 128 x 512 bf16 = 128 KB
static constexpr int SMEM_TOTAL = SMEM_C + MC * KC * 2;    // 196608

// ============================================================================
// Kernel 1: split-K bf16 GEMM (mma.sync) with fused conversion + sq-sums
// ============================================================================
__global__ void __launch_bounds__(512, 1)
svm_main_kernel(const float* __restrict__ x, const float* __restrict__ centers) {
    extern __shared__ char smem[];
    const uint32_t smem_base = smem_u32(smem);
    const int tid = threadIdx.x;
    const int wid = tid >> 5;
    const int lid = tid & 31;
    const int s   = blockIdx.x;
    const size_t k0 = (size_t)s * KC;

    // ---- convert x chunk: 64 rows, 8 threads/row, 16 float4 each ----
    {
        const int row = tid >> 3;
        const int sub = tid & 7;
        const float4* xp = reinterpret_cast<const float4*>(x + (size_t)row * 65536 + k0) + sub * 16;
        float acc = 0.f;
        #pragma unroll
        for (int i = 0; i < 16; i++) {
            float4 v = xp[i];
            acc += v.x * v.x + v.y * v.y + v.z * v.z + v.w * v.w;
            int k = sub * 64 + i * 4;
            uint2 pk = make_uint2(pack_bf16x2(v.x, v.y), pack_bf16x2(v.z, v.w));
            *reinterpret_cast<uint2*>(smem + SMEM_X + x_off(row, k)) = pk;
        }
        acc += __shfl_xor_sync(0xffffffffu, acc, 1);
        acc += __shfl_xor_sync(0xffffffffu, acc, 2);
        acc += __shfl_xor_sync(0xffffffffu, acc, 4);
        if (sub == 0) g_xsq_p[(size_t)row * S_SPLIT + s] = acc;
    }

    // ---- warp tile assignment: 4(M) x 4(N) grid, tile 32x16 ----
    const int mr = (wid >> 2) * 32;      // center-row base within block
    const int nb = (wid & 3) * 16;       // batch-col base

    // per-lane ldmatrix row/k components
    const int sel    = lid >> 3;
    const int l7     = lid & 7;
    const int a_row  = l7 + (sel & 1) * 8;    // + mr (+16 for second frag)
    const int a_kd   = (sel >> 1) * 8;
    const int b_row  = nb + l7 + (sel >> 1) * 8;
    const int b_kd   = (sel & 1) * 8;

    for (int blk = 0; blk < NCBLK; blk++) {
        // ---- convert centers block: 128 rows, 4 threads/row, 32 float4 each ----
        {
            const int row  = tid >> 2;
            const int sub  = tid & 3;
            const int grow = blk * MC + row;
            float acc = 0.f;
            if (grow < 500) {
                const float4* cp =
                    reinterpret_cast<const float4*>(centers + (size_t)grow * 65536 + k0) + sub * 32;
                #pragma unroll
                for (int i = 0; i < 32; i++) {
                    float4 v = cp[i];
                    acc += v.x * v.x + v.y * v.y + v.z * v.z + v.w * v.w;
                    int k = sub * 128 + i * 4;
                    uint2 pk = make_uint2(pack_bf16x2(v.x, v.y), pack_bf16x2(v.z, v.w));
                    *reinterpret_cast<uint2*>(smem + SMEM_C + c_off(row, k)) = pk;
                }
            } else {
                #pragma unroll
                for (int i = 0; i < 32; i++) {
                    int k = sub * 128 + i * 4;
                    *reinterpret_cast<uint2*>(smem + SMEM_C + c_off(row, k)) = make_uint2(0u, 0u);
                }
            }
            acc += __shfl_xor_sync(0xffffffffu, acc, 1);
            acc += __shfl_xor_sync(0xffffffffu, acc, 2);
            if (sub == 0) g_csq_p[(size_t)grow * S_SPLIT + s] = acc;
        }
        __syncthreads();

        // ---- MMA: D[32x16] per warp over KC=512 ----
        float acc[2][2][4];
        #pragma unroll
        for (int mi = 0; mi < 2; mi++)
            #pragma unroll
            for (int g = 0; g < 2; g++)
                #pragma unroll
                for (int i = 0; i < 4; i++) acc[mi][g][i] = 0.f;

        #pragma unroll 8
        for (int kk = 0; kk < KC; kk += 16) {
            uint32_t af0[4], af1[4], bf[4];
            ldsm_x4(af0, smem_base + SMEM_C + c_off(mr + a_row,      kk + a_kd));
            ldsm_x4(af1, smem_base + SMEM_C + c_off(mr + 16 + a_row, kk + a_kd));
            ldsm_x4(bf,  smem_base + SMEM_X + x_off(b_row,           kk + b_kd));
            mma_bf16(acc[0][0], af0, bf);
            mma_bf16(acc[0][1], af0, bf + 2);
            mma_bf16(acc[1][0], af1, bf);
            mma_bf16(acc[1][1], af1, bf + 2);
        }

        // ---- store partials: D[row=center, col=batch] ----
        {
            const int r0 = blk * MC + mr + (lid >> 2);
            const int c0 = nb + ((lid & 3) * 2);
            #pragma unroll
            for (int mi = 0; mi < 2; mi++) {
                #pragma unroll
                for (int g = 0; g < 2; g++) {
                    const int col = c0 + 8 * g;
                    float* base0 = g_part + (((size_t)(r0 + 16 * mi)     * S_SPLIT + s) << 6) + col;
                    float* base1 = g_part + (((size_t)(r0 + 16 * mi + 8) * S_SPLIT + s) << 6) + col;
                    *reinterpret_cast<float2*>(base0) = make_float2(acc[mi][g][0], acc[mi][g][1]);
                    *reinterpret_cast<float2*>(base1) = make_float2(acc[mi][g][2], acc[mi][g][3]);
                }
            }
        }
        __syncthreads();   // protect C smem before next block's conversion
    }
}

// ============================================================================
// Kernel 2: finalize ||c||^2 (rows 0..511) and ||x||^2 (rows 512..575)
// ============================================================================
__global__ void svm_sumsq_kernel() {
    const int row = blockIdx.x;
    const int lid = threadIdx.x;
    const float* src = (row < NCPAD) ? (g_csq_p + (size_t)row * S_SPLIT)
                                     : (g_xsq_p + (size_t)(row - NCPAD) * S_SPLIT);
    float v = src[lid] + src[lid + 32] + src[lid + 64] + src[lid + 96];
    #pragma unroll
    for (int d = 16; d > 0; d >>= 1) v += __shfl_xor_sync(0xffffffffu, v, d);
    if (lid == 0) {
        if (row < NCPAD) g_csq[row] = v;
        else             g_xsq[row - NCPAD] = v;
    }
}

// ============================================================================
// Kernel 3: reduce cross partials over S, compute rbf[b][c]
// ============================================================================
__global__ void svm_rbf_kernel() {
    __shared__ float red[4][NB];
    const int c   = blockIdx.x;          // 0..499
    const int tid = threadIdx.x;         // 256
    const int sp  = tid >> 6;
    const int b   = tid & 63;
    const float* p = g_part + ((size_t)c * S_SPLIT + (size_t)sp * 32) * NB + b;
    float a = 0.f;
    #pragma unroll
    for (int i = 0; i < 32; i++) a += p[(size_t)i * NB];
    red[sp][b] = a;
    __syncthreads();
    if (tid < NB) {
        float cross = red[0][tid] + red[1][tid] + red[2][tid] + red[3][tid];
        float dist  = g_xsq[tid] - 2.0f * cross + g_csq[c];
        g_rbf[(size_t)tid * NCPAD + c] = expf(-GAMMA_F * dist);
    }
}

// ============================================================================
// Kernel 4: out[b][i] = sum_c rbf[b][c] * fc_w[i][c] + fc_b[i]
// ============================================================================
__global__ void svm_fc_kernel(const float* __restrict__ fc_w,
                              const float* __restrict__ fc_b,
                              float* __restrict__ out) {
    const int b   = blockIdx.x;          // 0..63
    const int wid = threadIdx.x >> 5;    // 0..7
    const int lid = threadIdx.x & 31;
    const float* rr = g_rbf + (size_t)b * NCPAD;
    float acc = 0.f;
    for (int c = lid; c < 500; c += 32)
        acc += rr[c] * fc_w[wid * 500 + c];
    #pragma unroll
    for (int d = 16; d > 0; d >>= 1) acc += __shfl_xor_sync(0xffffffffu, acc, d);
    if (lid == 0) out[b * 8 + wid] = acc + fc_b[wid];
}

// ============================================================================
extern "C" void kernel_launch(void* const* d_in, const int* in_sizes, int n_in,
                              void* d_out, int out_size) {
    const float* x       = (const float*)d_in[0];
    const float* centers = (const float*)d_in[1];
    const float* fc_w    = (const float*)d_in[2];
    const float* fc_b    = (const float*)d_in[3];
    float* out = (float*)d_out;

    cudaFuncSetAttribute(svm_main_kernel, cudaFuncAttributeMaxDynamicSharedMemorySize, SMEM_TOTAL);

    svm_main_kernel<<<S_SPLIT, 512, SMEM_TOTAL>>>(x, centers);
    svm_sumsq_kernel<<<NCPAD + NB, 32>>>();
    svm_rbf_kernel<<<500, 256>>>();
    svm_fc_kernel<<<NB, 256>>>(fc_w, fc_b, out);
}